// round 4
// baseline (speedup 1.0000x reference)
#include <cuda_runtime.h>
#include <math.h>

// ---------------------------------------------------------------------------
// CoDAConv2d rewritten:
//   act_o  = sum_c x_c * (A_o^T nb)_c + nb.b_o
//   norm_o = sqrt(x^T G_o x + 2 u_o^T x + s_o) + eps
// Thread t=(o,c). f32x2 packed FMA; F table in SMEM (streamed); 4px blocking;
// 8-value/8-lane butterfly reduction; rsqrt epilogue; atomic task scheduler.
// ---------------------------------------------------------------------------

#define B_  4
#define CI  8
#define CO  16
#define HH  112
#define WW  112
#define PATCH 72
#define EPS 1e-6f

#define CHUNK 16
#define COLS  (CHUNK + 2)               // 18
#define TILE_ELEMS (3 * COLS * 8)       // 432
#define NCHUNK (WW / CHUNK)             // 7
#define NTASK  (B_ * HH * NCHUNK)       // 3136
#define GRID   592                      // 148 SMs * 4 blocks

typedef unsigned long long ull;

// packed-pair tables
__device__ ull   gF2[36 * 128];   // [i*9+j][t] : (F[c'=2i], F[c'=2i+1]) at tap j
__device__ float gZ[9 * 128];     // bias-conv taps
__device__ ull   gQ2[4 * 128];    // (G[c][2k],G[c][2k+1])
__device__ float gU[128];         // 2*u[o][c]
__device__ float gS[128];         // s[o]/8
__device__ int   gCtr;

// --- f32x2 helpers -----------------------------------------------------------
__device__ __forceinline__ ull ffma2(ull a, ull b, ull c) {
    ull d; asm("fma.rn.f32x2 %0, %1, %2, %3;" : "=l"(d) : "l"(a), "l"(b), "l"(c));
    return d;
}
__device__ __forceinline__ ull fadd2(ull a, ull b) {
    ull d; asm("add.rn.f32x2 %0, %1, %2;" : "=l"(d) : "l"(a), "l"(b));
    return d;
}
__device__ __forceinline__ ull pack2(float lo, float hi) {
    ull d; asm("mov.b64 %0, {%1, %2};" : "=l"(d) : "f"(lo), "f"(hi));
    return d;
}
__device__ __forceinline__ float hsum2(ull a) {
    float lo, hi; asm("mov.b64 {%0, %1}, %2;" : "=f"(lo), "=f"(hi) : "l"(a));
    return lo + hi;
}

// --- prep kernel ---------------------------------------------------------------
__global__ void coda_prep_kernel(const float* __restrict__ w_pred,
                                 const float* __restrict__ b_pred) {
    const int bx  = blockIdx.x;
    const int tid = threadIdx.x;
    if (bx == 0 && tid == 0) gCtr = 0;

    if (bx < 36) {
        const int i = bx / 9, j = bx % 9;
        const int o = tid >> 3, c = tid & 7;
        float lo = w_pred[(((2 * i)     * 9 + j) * 16 + o) * 8 + c];
        float hi = w_pred[(((2 * i + 1) * 9 + j) * 16 + o) * 8 + c];
        gF2[bx * 128 + tid] = pack2(lo, hi);
        if (bx < 9) gZ[bx * 128 + tid] = b_pred[(c * 9 + bx) * 16 + o];
        return;
    }

    // Gram part: one block per output channel o
    const int o = bx - 36;
    __shared__ float sw[PATCH][8];
    __shared__ float sb[PATCH];
    __shared__ float sG[8][8];

    for (int idx = tid; idx < PATCH * 8; idx += 128) {
        int p = idx >> 3, cc = idx & 7;
        sw[p][cc] = w_pred[(p * 16 + o) * 8 + cc];
    }
    for (int idx = tid; idx < PATCH; idx += 128)
        sb[idx] = b_pred[idx * 16 + o];
    __syncthreads();

    if (tid < 64) {
        const int c = tid >> 3, k = tid & 7;
        float acc = 0.f;
        #pragma unroll 8
        for (int p = 0; p < PATCH; p++) acc = fmaf(sw[p][c], sw[p][k], acc);
        sG[c][k] = acc;

        if (k == 0) {
            float u = 0.f;
            #pragma unroll 8
            for (int p = 0; p < PATCH; p++) u = fmaf(sw[p][c], sb[p], u);
            gU[o * 8 + c] = 2.0f * u;
        }
        if (tid == 0) {
            float s = 0.f;
            #pragma unroll 8
            for (int p = 0; p < PATCH; p++) s = fmaf(sb[p], sb[p], s);
            s *= 0.125f;
            #pragma unroll
            for (int cc = 0; cc < 8; cc++) gS[o * 8 + cc] = s;
        }
    }
    __syncthreads();
    if (tid < 8) {
        #pragma unroll
        for (int kk = 0; kk < 4; kk++)
            gQ2[kk * 128 + o * 8 + tid] = pack2(sG[tid][2 * kk], sG[tid][2 * kk + 1]);
    }
}

// --- prefetch loader --------------------------------------------------------
__device__ __forceinline__ void load_task(const float* __restrict__ in,
                                          int task, int t, float pre[4]) {
    const int rowid = task / NCHUNK;
    const int cw    = (task % NCHUNK) * CHUNK;
    const int b     = rowid / HH;
    const int h     = rowid % HH;
    #pragma unroll
    for (int k = 0; k < 4; k++) {
        int idx = t + k * 128;
        float v = 0.f;
        if (idx < TILE_ELEMS) {
            int ch   = idx & 7;
            int rest = idx >> 3;
            int col  = rest % COLS;
            int r    = rest / COLS;
            int ir   = h - 1 + r;
            int ic   = cw - 1 + col;
            if ((unsigned)ir < (unsigned)HH && (unsigned)ic < (unsigned)WW)
                v = __ldg(&in[((b * CI + ch) * HH + ir) * WW + ic]);
        }
        pre[k] = v;
    }
}

// --- main kernel ----------------------------------------------------------------
__global__ __launch_bounds__(128, 4)
void coda_main_kernel(const float* __restrict__ in, float* __restrict__ out) {
    const int t = threadIdx.x;
    const int c = t & 7;
    const int o = t >> 3;

    __shared__ ull   sF[36 * 128];      // 36 KB: per-thread F columns
    __shared__ float tile[3][COLS][8];
    __shared__ int   sTask;

    // stage F table into smem (coalesced, L2-resident source)
    #pragma unroll
    for (int p = 0; p < 36; p++) sF[p * 128 + t] = gF2[p * 128 + t];

    float Zreg[9];
    #pragma unroll
    for (int j = 0; j < 9; j++) Zreg[j] = gZ[j * 128 + t];
    ull Qp[4];
    #pragma unroll
    for (int k = 0; k < 4; k++) Qp[k] = gQ2[k * 128 + t];
    const ull   qinit = pack2(gU[t], 0.f);
    const float Qs    = gS[t];

    float pre[4];

    if (t == 0) sTask = atomicAdd(&gCtr, 1);
    __syncthreads();                     // also covers sF visibility
    int task = sTask;
    if (task >= NTASK) return;
    load_task(in, task, t, pre);

    while (true) {
        #pragma unroll
        for (int k = 0; k < 4; k++) {
            int idx = t + k * 128;
            if (idx < TILE_ELEMS) ((float*)tile)[idx] = pre[k];
        }
        if (t == 0) sTask = atomicAdd(&gCtr, 1);
        __syncthreads();
        const int nxt = sTask;
        if (nxt < NTASK) load_task(in, nxt, t, pre);

        const int rowid = task / NCHUNK;
        const int cw    = (task % NCHUNK) * CHUNK;
        const int b     = rowid / HH;
        const int h     = rowid % HH;
        float* orow = &out[((b * CO + o) * HH + h) * WW + cw];

        #pragma unroll 1
        for (int wlb = 0; wlb < CHUNK; wlb += 4) {
            ull  m0[4], m1[4];
            float z[4], xc[4];
            ull  qp[4];
            #pragma unroll
            for (int px = 0; px < 4; px++) { m0[px] = 0ull; m1[px] = 0ull; z[px] = 0.f; }

            #pragma unroll
            for (int dh = 0; dh < 3; dh++) {
                // stream this dh-row of F: taps j = 3*dh..3*dh+2 for 4 channel pairs
                ull Fr[12];
                #pragma unroll
                for (int i = 0; i < 4; i++)
                    #pragma unroll
                    for (int jj = 0; jj < 3; jj++)
                        Fr[i * 3 + jj] = sF[(i * 9 + dh * 3 + jj) * 128 + t];

                #pragma unroll
                for (int k = 0; k < 6; k++) {
                    const float* pv = &tile[dh][wlb + k][0];
                    const ulonglong2 VA = *(const ulonglong2*)pv;       // (c0,c1),(c2,c3)
                    const ulonglong2 VB = *((const ulonglong2*)pv + 1); // (c4,c5),(c6,c7)
                    const float vc = pv[c];

                    const int pxlo = (k - 2 > 0) ? (k - 2) : 0;
                    const int pxhi = (k < 3) ? k : 3;
                    #pragma unroll
                    for (int px = pxlo; px <= pxhi; px++) {
                        const int jj = k - px;                // 0..2
                        m0[px] = ffma2(VA.x, Fr[0 + jj], m0[px]);
                        m0[px] = ffma2(VA.y, Fr[3 + jj], m0[px]);
                        m1[px] = ffma2(VB.x, Fr[6 + jj], m1[px]);
                        m1[px] = ffma2(VB.y, Fr[9 + jj], m1[px]);
                        z[px]  = fmaf(vc, Zreg[dh * 3 + jj], z[px]);
                    }
                    if (dh == 1 && k >= 1 && k <= 4) {
                        const int px = k - 1;
                        xc[px] = vc;
                        ull qa = ffma2(VA.x, Qp[0], qinit);
                        qa = ffma2(VB.x, Qp[2], qa);
                        ull qb = ffma2(VA.y, Qp[1], 0ull);
                        qb = ffma2(VB.y, Qp[3], qb);
                        qp[px] = fadd2(qa, qb);
                    }
                }
            }

            // per-pixel scalars
            float r[8];
            #pragma unroll
            for (int px = 0; px < 4; px++) {
                float m = hsum2(fadd2(m0[px], m1[px]));
                r[px]     = fmaf(xc[px], m, z[px]);            // av partial
                r[px + 4] = fmaf(xc[px], hsum2(qp[px]), Qs);   // qv partial
            }

            // 8-value / 8-lane butterfly reduction: lane c ends with sum of r[c]
            const bool h0 = c & 1, h1 = c & 2, h2 = c & 4;
            float s4[4];
            #pragma unroll
            for (int i = 0; i < 4; i++) {
                float give = h0 ? r[2 * i] : r[2 * i + 1];
                float got  = __shfl_xor_sync(0xffffffffu, give, 1);
                s4[i] = (h0 ? r[2 * i + 1] : r[2 * i]) + got;
            }
            float u2[2];
            #pragma unroll
            for (int i = 0; i < 2; i++) {
                float give = h1 ? s4[2 * i] : s4[2 * i + 1];
                float got  = __shfl_xor_sync(0xffffffffu, give, 2);
                u2[i] = (h1 ? s4[2 * i + 1] : s4[2 * i]) + got;
            }
            {
                float give = h2 ? u2[0] : u2[1];
                float got  = __shfl_xor_sync(0xffffffffu, give, 4);
                float tot  = (h2 ? u2[1] : u2[0]) + got;     // lane c: sum of r[c]
                float other = __shfl_xor_sync(0xffffffffu, tot, 4);
                if (c < 4) {
                    // reference denom = sqrt(qv)+1e-6; qv bounded well away from 0,
                    // so av * rsqrt(qv) is within ~1e-5 relative of it.
                    float qv = fmaxf(other, 1e-20f);
                    orow[wlb + c] = tot * rsqrtf(qv);
                }
            }
        }

        __syncthreads();
        if (nxt >= NTASK) return;
        task = nxt;
    }
}

// ---------------------------------------------------------------------------
extern "C" void kernel_launch(void* const* d_in, const int* in_sizes, int n_in,
                              void* d_out, int out_size) {
    const float* in_tensor = (const float*)d_in[0];
    const float* w_pred    = (const float*)d_in[1];
    const float* b_pred    = (const float*)d_in[2];
    float* out = (float*)d_out;

    coda_prep_kernel<<<36 + CO, 128>>>(w_pred, b_pred);
    coda_main_kernel<<<GRID, 128>>>(in_tensor, out);
}

// round 5
// speedup vs baseline: 1.1751x; 1.1751x over previous
#include <cuda_runtime.h>
#include <math.h>

// ---------------------------------------------------------------------------
// CoDAConv2d rewritten:
//   act_o  = sum_c x_c * (A_o^T nb)_c + nb.b_o
//   norm_o = sqrt(x^T G_o x + 2 u_o^T x + s_o) + eps
// Thread t=(o,c,s): 16 o x 8 c x 2 s = 256 threads. s splits the 4 packed
// channel pairs of the contraction (s=0: pairs 0,1; s=1: pairs 2,3), halving
// per-thread F registers -> 2 CTAs/SM, 16 warps. f32x2 packed FMA; 4px
// register blocking; 8-value/16-lane butterfly reduction; rsqrt epilogue.
// ---------------------------------------------------------------------------

#define B_  4
#define CI  8
#define CO  16
#define HH  112
#define WW  112
#define PATCH 72

#define CHUNK 16
#define COLS  (CHUNK + 2)               // 18
#define TILE_ELEMS (3 * COLS * 8)       // 432
#define NCHUNK (WW / CHUNK)             // 7
#define NTASK  (B_ * HH * NCHUNK)       // 3136
#define NT 256
#define GRID   296                      // 148 SMs * 2 blocks

typedef unsigned long long ull;

// packed-pair tables (index tid127 = o*8+c)
__device__ ull   gF2[36 * 128];   // [i*9+j][t] : (F[c'=2i], F[c'=2i+1]) at tap j
__device__ float gZ[9 * 128];     // bias-conv taps
__device__ ull   gQ2[4 * 128];    // (G[c][2k],G[c][2k+1])
__device__ float gU[128];         // 2*u[o][c]
__device__ float gS[128];         // s[o]/8
__device__ int   gCtr;

// --- f32x2 helpers -----------------------------------------------------------
__device__ __forceinline__ ull ffma2(ull a, ull b, ull c) {
    ull d; asm("fma.rn.f32x2 %0, %1, %2, %3;" : "=l"(d) : "l"(a), "l"(b), "l"(c));
    return d;
}
__device__ __forceinline__ ull fadd2(ull a, ull b) {
    ull d; asm("add.rn.f32x2 %0, %1, %2;" : "=l"(d) : "l"(a), "l"(b));
    return d;
}
__device__ __forceinline__ ull pack2(float lo, float hi) {
    ull d; asm("mov.b64 %0, {%1, %2};" : "=l"(d) : "f"(lo), "f"(hi));
    return d;
}
__device__ __forceinline__ float hsum2(ull a) {
    float lo, hi; asm("mov.b64 {%0, %1}, %2;" : "=f"(lo), "=f"(hi) : "l"(a));
    return lo + hi;
}

// --- prep kernel ---------------------------------------------------------------
__global__ void coda_prep_kernel(const float* __restrict__ w_pred,
                                 const float* __restrict__ b_pred) {
    const int bx  = blockIdx.x;
    const int tid = threadIdx.x;
    if (bx == 0 && tid == 0) gCtr = 0;

    if (bx < 36) {
        const int i = bx / 9, j = bx % 9;
        const int o = tid >> 3, c = tid & 7;
        float lo = w_pred[(((2 * i)     * 9 + j) * 16 + o) * 8 + c];
        float hi = w_pred[(((2 * i + 1) * 9 + j) * 16 + o) * 8 + c];
        gF2[bx * 128 + tid] = pack2(lo, hi);
        if (bx < 9) gZ[bx * 128 + tid] = b_pred[(c * 9 + bx) * 16 + o];
        return;
    }

    // Gram part: one block per output channel o
    const int o = bx - 36;
    __shared__ float sw[PATCH][8];
    __shared__ float sb[PATCH];
    __shared__ float sG[8][8];

    for (int idx = tid; idx < PATCH * 8; idx += 128) {
        int p = idx >> 3, cc = idx & 7;
        sw[p][cc] = w_pred[(p * 16 + o) * 8 + cc];
    }
    for (int idx = tid; idx < PATCH; idx += 128)
        sb[idx] = b_pred[idx * 16 + o];
    __syncthreads();

    if (tid < 64) {
        const int c = tid >> 3, k = tid & 7;
        float acc = 0.f;
        #pragma unroll 8
        for (int p = 0; p < PATCH; p++) acc = fmaf(sw[p][c], sw[p][k], acc);
        sG[c][k] = acc;

        if (k == 0) {
            float u = 0.f;
            #pragma unroll 8
            for (int p = 0; p < PATCH; p++) u = fmaf(sw[p][c], sb[p], u);
            gU[o * 8 + c] = 2.0f * u;
        }
        if (tid == 0) {
            float s = 0.f;
            #pragma unroll 8
            for (int p = 0; p < PATCH; p++) s = fmaf(sb[p], sb[p], s);
            s *= 0.125f;
            #pragma unroll
            for (int cc = 0; cc < 8; cc++) gS[o * 8 + cc] = s;
        }
    }
    __syncthreads();
    if (tid < 8) {
        #pragma unroll
        for (int kk = 0; kk < 4; kk++)
            gQ2[kk * 128 + o * 8 + tid] = pack2(sG[tid][2 * kk], sG[tid][2 * kk + 1]);
    }
}

// --- prefetch loader (256 threads, 2 regs each) -------------------------------
__device__ __forceinline__ void load_task(const float* __restrict__ in,
                                          int task, int t, float pre[2]) {
    const int rowid = task / NCHUNK;
    const int cw    = (task % NCHUNK) * CHUNK;
    const int b     = rowid / HH;
    const int h     = rowid % HH;
    #pragma unroll
    for (int k = 0; k < 2; k++) {
        int idx = t + k * NT;
        float v = 0.f;
        if (idx < TILE_ELEMS) {
            int ch   = idx & 7;
            int rest = idx >> 3;
            int col  = rest % COLS;
            int r    = rest / COLS;
            int ir   = h - 1 + r;
            int ic   = cw - 1 + col;
            if ((unsigned)ir < (unsigned)HH && (unsigned)ic < (unsigned)WW)
                v = __ldg(&in[((b * CI + ch) * HH + ir) * WW + ic]);
        }
        pre[k] = v;
    }
}

// --- main kernel ----------------------------------------------------------------
__global__ __launch_bounds__(NT, 2)
void coda_main_kernel(const float* __restrict__ in, float* __restrict__ out) {
    const int t    = threadIdx.x;
    const int c    = t & 7;
    const int s    = (t >> 3) & 1;
    const int o    = t >> 4;
    const int t127 = o * 8 + c;

    // per-thread constant tables: only this s-half's channel pairs
    ull Fp[18];                          // [pair e][tap j] -> Fp[e*9+j]
    #pragma unroll
    for (int e = 0; e < 2; e++)
        #pragma unroll
        for (int j = 0; j < 9; j++)
            Fp[e * 9 + j] = gF2[((2 * s + e) * 9 + j) * 128 + t127];

    float Zreg[9];
    #pragma unroll
    for (int j = 0; j < 9; j++) Zreg[j] = s ? 0.f : gZ[j * 128 + t127];

    ull Qp[2];
    #pragma unroll
    for (int e = 0; e < 2; e++) Qp[e] = gQ2[(2 * s + e) * 128 + t127];
    const ull   qinit = s ? 0ull : pack2(gU[t127], 0.f);
    const float Qs    = gS[t127] * 0.5f;     // s[o]/16, summed over 16 lanes

    __shared__ float tile[3][COLS][8];
    __shared__ int   sTask;

    float pre[2];

    if (t == 0) sTask = atomicAdd(&gCtr, 1);
    __syncthreads();
    int task = sTask;
    if (task >= NTASK) return;
    load_task(in, task, t, pre);

    while (true) {
        #pragma unroll
        for (int k = 0; k < 2; k++) {
            int idx = t + k * NT;
            if (idx < TILE_ELEMS) ((float*)tile)[idx] = pre[k];
        }
        if (t == 0) sTask = atomicAdd(&gCtr, 1);
        __syncthreads();
        const int nxt = sTask;
        if (nxt < NTASK) load_task(in, nxt, t, pre);

        const int rowid = task / NCHUNK;
        const int cw    = (task % NCHUNK) * CHUNK;
        const int b     = rowid / HH;
        const int h     = rowid % HH;
        float* orow = &out[((b * CO + o) * HH + h) * WW + cw];

        #pragma unroll 1
        for (int wlb = 0; wlb < CHUNK; wlb += 4) {
            ull  m0[4], m1[4];
            float z[4], xc[4];
            ull  qp[4];
            #pragma unroll
            for (int px = 0; px < 4; px++) { m0[px] = 0ull; m1[px] = 0ull; z[px] = 0.f; }

            #pragma unroll
            for (int dh = 0; dh < 3; dh++) {
                #pragma unroll
                for (int k = 0; k < 6; k++) {
                    const float* pv = &tile[dh][wlb + k][0];
                    const ulonglong2 V = ((const ulonglong2*)pv)[s]; // this half's 2 pairs
                    const float vc = pv[c];

                    const int pxlo = (k - 2 > 0) ? (k - 2) : 0;
                    const int pxhi = (k < 3) ? k : 3;
                    #pragma unroll
                    for (int px = pxlo; px <= pxhi; px++) {
                        const int j = dh * 3 + (k - px);
                        m0[px] = ffma2(V.x, Fp[0 + j], m0[px]);
                        m1[px] = ffma2(V.y, Fp[9 + j], m1[px]);
                        z[px]  = fmaf(vc, Zreg[j], z[px]);   // Zreg=0 on s=1
                    }
                    if (dh == 1 && k >= 1 && k <= 4) {
                        const int px = k - 1;
                        xc[px] = vc;
                        qp[px] = fadd2(ffma2(V.x, Qp[0], qinit),
                                       ffma2(V.y, Qp[1], 0ull));
                    }
                }
            }

            // per-pixel scalars: r[0..3]=av partial, r[4..7]=qv partial
            float r[8];
            #pragma unroll
            for (int px = 0; px < 4; px++) {
                float m = hsum2(fadd2(m0[px], m1[px]));
                r[px]     = fmaf(xc[px], m, z[px]);
                r[px + 4] = fmaf(xc[px], hsum2(qp[px]), Qs);
            }

            // 8-value butterfly over lane bits 0..2 (c), then bit 3 (s)
            const bool h0 = c & 1, h1 = c & 2, h2 = c & 4;
            float s4[4];
            #pragma unroll
            for (int i = 0; i < 4; i++) {
                float give = h0 ? r[2 * i] : r[2 * i + 1];
                float got  = __shfl_xor_sync(0xffffffffu, give, 1);
                s4[i] = (h0 ? r[2 * i + 1] : r[2 * i]) + got;
            }
            float u2[2];
            #pragma unroll
            for (int i = 0; i < 2; i++) {
                float give = h1 ? s4[2 * i] : s4[2 * i + 1];
                float got  = __shfl_xor_sync(0xffffffffu, give, 2);
                u2[i] = (h1 ? s4[2 * i + 1] : s4[2 * i]) + got;
            }
            {
                float give = h2 ? u2[0] : u2[1];
                float got  = __shfl_xor_sync(0xffffffffu, give, 4);
                float tot  = (h2 ? u2[1] : u2[0]) + got;      // half-sum of r[c]
                tot += __shfl_xor_sync(0xffffffffu, tot, 8);  // add other s-half
                float other = __shfl_xor_sync(0xffffffffu, tot, 4);
                if (c < 4 && s == 0) {
                    // reference denom = sqrt(qv)+1e-6; qv bounded away from 0,
                    // so av * rsqrt(qv) is within ~1e-5 relative of it.
                    float qv = fmaxf(other, 1e-20f);
                    orow[wlb + c] = tot * rsqrtf(qv);
                }
            }
        }

        __syncthreads();
        if (nxt >= NTASK) return;
        task = nxt;
    }
}

// ---------------------------------------------------------------------------
extern "C" void kernel_launch(void* const* d_in, const int* in_sizes, int n_in,
                              void* d_out, int out_size) {
    const float* in_tensor = (const float*)d_in[0];
    const float* w_pred    = (const float*)d_in[1];
    const float* b_pred    = (const float*)d_in[2];
    float* out = (float*)d_out;

    coda_prep_kernel<<<36 + CO, 128>>>(w_pred, b_pred);
    coda_main_kernel<<<GRID, NT>>>(in_tensor, out);
}